// round 17
// baseline (speedup 1.0000x reference)
#include <cuda_runtime.h>

#define HID 8
typedef unsigned long long u64;
typedef unsigned int u32;

// ---- weights in constant memory: warp-uniform, immediate offsets -> LDCU path ----
__constant__ __align__(16) float cWi_r[16];
__constant__ __align__(16) float cWh_r[64];
__constant__ __align__(16) float cbh_r[8];
__constant__ __align__(16) float cWi_z[16];
__constant__ __align__(16) float cWh_z[64];
__constant__ __align__(16) float cbh_z[8];
__constant__ __align__(16) float cWi_n[16];
__constant__ __align__(16) float cWh_n[64];
__constant__ __align__(16) float cbh_n[8];
__constant__ __align__(16) float cWm[8];
__constant__ __align__(16) float cbm[4];

// 8-byte constant load of an adjacent weight pair (element index must be even).
#define LDC2(arr, idx) (*reinterpret_cast<const u64*>(&(arr)[idx]))

// ---- f32x2 packed helpers (sm_103a) ----
__device__ __forceinline__ u64 pk2(float a, float b) {
    u64 r; asm("mov.b64 %0, {%1, %2};" : "=l"(r) : "f"(a), "f"(b)); return r;
}
__device__ __forceinline__ void upk2(u64 v, float& a, float& b) {
    asm("mov.b64 {%0, %1}, %2;" : "=f"(a), "=f"(b) : "l"(v));
}
__device__ __forceinline__ u64 fma2(u64 a, u64 b, u64 c) {
    u64 d; asm("fma.rn.f32x2 %0, %1, %2, %3;" : "=l"(d) : "l"(a), "l"(b), "l"(c)); return d;
}
__device__ __forceinline__ u64 mul2(u64 a, u64 b) {
    u64 d; asm("mul.rn.f32x2 %0, %1, %2;" : "=l"(d) : "l"(a), "l"(b)); return d;
}
// Packed two-lane tanh (tanh.approx is scalar; pair halves split in-asm).
__device__ __forceinline__ u64 tanh2(u64 x) {
    u64 y;
    asm("{\n\t"
        ".reg .f32 lo, hi, tl, th;\n\t"
        "mov.b64 {lo, hi}, %1;\n\t"
        "tanh.approx.f32 tl, lo;\n\t"
        "tanh.approx.f32 th, hi;\n\t"
        "mov.b64 %0, {tl, th};\n\t"
        "}" : "=l"(y) : "l"(x));
    return y;
}
// Build (lo(x), lo(y)) — turn broadcast h regs back into a column pair.
__device__ __forceinline__ u64 mergelo(u64 x, u64 y) {
    u64 r;
    asm("{\n\t"
        ".reg .f32 xl, xh, yl, yh;\n\t"
        "mov.b64 {xl, xh}, %1;\n\t"
        "mov.b64 {yl, yh}, %2;\n\t"
        "mov.b64 %0, {xl, yl};\n\t"
        "}" : "=l"(r) : "l"(x), "l"(y));
    return r;
}
// 16B global store of two packed pairs — one STG.128 instead of two STG.64.
__device__ __forceinline__ void stg2(void* p, u64 a, u64 b) {
    asm volatile("st.global.v2.u64 [%0], {%1, %2};" :: "l"(p), "l"(a), "l"(b) : "memory");
}

#define TPB 128
#define ROWS_PER_BLOCK (TPB * 2)

__global__ void __launch_bounds__(TPB, 6)
l2o_gru_kernel(const float* __restrict__ h, const float* __restrict__ g,
               float* __restrict__ out_h, float* __restrict__ out_o, int N)
{
    const int t = threadIdx.x;

    // Two rows per thread (R, S); lanes of each f32x2 are adjacent COLUMNS.
    const int base = blockIdx.x * ROWS_PER_BLOCK;
    const int rowR = base + t;
    const int rowS = base + TPB + t;
    const int rcR = rowR < N ? rowR : (N - 1);
    const int rcS = rowS < N ? rowS : (N - 1);
    const bool okR = rowR < N;
    const bool okS = rowS < N;

    // Broadcast h registers: hbX[k] = (h[k], h[k]).
    u64 hbR[HID], hbS[HID];
    {
        const float4* p0 = reinterpret_cast<const float4*>(h + (size_t)rcR * HID);
        float4 a0 = __ldg(p0), a1 = __ldg(p0 + 1);
        hbR[0] = pk2(a0.x, a0.x); hbR[1] = pk2(a0.y, a0.y);
        hbR[2] = pk2(a0.z, a0.z); hbR[3] = pk2(a0.w, a0.w);
        hbR[4] = pk2(a1.x, a1.x); hbR[5] = pk2(a1.y, a1.y);
        hbR[6] = pk2(a1.z, a1.z); hbR[7] = pk2(a1.w, a1.w);
        const float4* p1 = reinterpret_cast<const float4*>(h + (size_t)rcS * HID);
        float4 b0 = __ldg(p1), b1 = __ldg(p1 + 1);
        hbS[0] = pk2(b0.x, b0.x); hbS[1] = pk2(b0.y, b0.y);
        hbS[2] = pk2(b0.z, b0.z); hbS[3] = pk2(b0.w, b0.w);
        hbS[4] = pk2(b1.x, b1.x); hbS[5] = pk2(b1.y, b1.y);
        hbS[6] = pk2(b1.z, b1.z); hbS[7] = pk2(b1.w, b1.w);
    }

    float gR = __ldg(g + rcR);
    float gS = __ldg(g + rcS);
    u64 gbR0, gbR1, gbS0, gbS1;
    {
        const float EXPP = 22026.4658203125f;  // exp(10)
        float glR = __logf(fabsf(gR) + 1e-8f) * 0.1f;
        float glS = __logf(fabsf(gS) + 1e-8f) * 0.1f;
        float sgR = (gR > 0.0f) ? 1.0f : ((gR < 0.0f) ? -1.0f : 0.0f);
        float sgS = (gS > 0.0f) ? 1.0f : ((gS < 0.0f) ? -1.0f : 0.0f);
        float i0R, i1R, i0S, i1S;
        if (glR >= -1.0f) { i0R = glR;   i1R = sgR; }
        else              { i0R = -1.0f; i1R = EXPP * gR; }
        if (glS >= -1.0f) { i0S = glS;   i1S = sgS; }
        else              { i0S = -1.0f; i1S = EXPP * gS; }
        gbR0 = pk2(i0R, i0R); gbR1 = pk2(i1R, i1R);
        gbS0 = pk2(i0S, i0S); gbS1 = pk2(i1S, i1S);
    }

    const u64 half2 = 0x3F0000003F000000ULL;  // (0.5f, 0.5f)
    const u64 neg12 = 0xBF800000BF800000ULL;  // (-1.f, -1.f)

    u64 outsR = pk2(cbm[0], 0.0f);   // bm in even-lane; horizontal add at the end
    u64 outsS = outsR;

    char* ohR = reinterpret_cast<char*>(out_h + (size_t)rowR * HID);
    char* ohS = reinterpret_cast<char*>(out_h + (size_t)rowS * HID);

    u64 prevR = 0, prevS = 0;   // even-jp hn2, stored at the following odd jp

    #pragma unroll
    for (int jp = 0; jp < 4; jp++) {
        const int c = 2 * jp;
        u64 w0, w1, w2;
        u64 arR, azR, anR, winR, arS, azS, anS, winS;

        // r gate
        w0 = LDC2(cbh_r, c);
        w1 = LDC2(cWi_r, c);
        w2 = LDC2(cWi_r, 8 + c);
        arR = fma2(gbR0, w1, w0);           arS = fma2(gbS0, w1, w0);
        arR = fma2(gbR1, w2, arR);          arS = fma2(gbS1, w2, arS);
        #pragma unroll
        for (int k = 0; k < HID; k++) {
            u64 w = LDC2(cWh_r, k * HID + c);
            arR = fma2(hbR[k], w, arR);     arS = fma2(hbS[k], w, arS);
        }

        // z gate
        w0 = LDC2(cbh_z, c);
        w1 = LDC2(cWi_z, c);
        w2 = LDC2(cWi_z, 8 + c);
        azR = fma2(gbR0, w1, w0);           azS = fma2(gbS0, w1, w0);
        azR = fma2(gbR1, w2, azR);          azS = fma2(gbS1, w2, azS);
        #pragma unroll
        for (int k = 0; k < HID; k++) {
            u64 w = LDC2(cWh_z, k * HID + c);
            azR = fma2(hbR[k], w, azR);     azS = fma2(hbS[k], w, azS);
        }

        // n gate
        w0 = LDC2(cbh_n, c);
        w1 = LDC2(cWi_n, c);
        w2 = LDC2(cWi_n, 8 + c);
        winR = mul2(gbR0, w1);              winS = mul2(gbS0, w1);
        winR = fma2(gbR1, w2, winR);        winS = fma2(gbS1, w2, winS);
        anR = w0;                           anS = w0;
        #pragma unroll
        for (int k = 0; k < HID; k++) {
            u64 w = LDC2(cWh_n, k * HID + c);
            anR = fma2(hbR[k], w, anR);     anS = fma2(hbS[k], w, anS);
        }

        u64 wm = LDC2(cWm, c);

        // Packed epilogue; hn pairs buffered and stored as 16B v2.u64 at odd jp.
        {
            u64 r2 = fma2(tanh2(mul2(arR, half2)), half2, half2);
            u64 z2 = fma2(tanh2(mul2(azR, half2)), half2, half2);
            u64 n2 = tanh2(fma2(r2, anR, winR));
            u64 hpr = mergelo(hbR[c], hbR[c + 1]);             // (h[2jp], h[2jp+1])
            u64 hn2 = fma2(z2, fma2(n2, neg12, hpr), n2);      // n + z*(h-n)
            if (jp & 1) { if (okR) stg2(ohR + (jp - 1) * 8, prevR, hn2); }
            else        prevR = hn2;
            outsR = fma2(hn2, wm, outsR);
        }
        {
            u64 r2 = fma2(tanh2(mul2(arS, half2)), half2, half2);
            u64 z2 = fma2(tanh2(mul2(azS, half2)), half2, half2);
            u64 n2 = tanh2(fma2(r2, anS, winS));
            u64 hps = mergelo(hbS[c], hbS[c + 1]);
            u64 hn2 = fma2(z2, fma2(n2, neg12, hps), n2);
            if (jp & 1) { if (okS) stg2(ohS + (jp - 1) * 8, prevS, hn2); }
            else        prevS = hn2;
            outsS = fma2(hn2, wm, outsS);
        }
    }

    float eR, oR, eS, oS;
    upk2(outsR, eR, oR);
    upk2(outsS, eS, oS);
    if (okR) out_o[rowR] = -__expf(eR + oR) * gR;
    if (okS) out_o[rowS] = -__expf(eS + oS) * gS;
}

extern "C" void kernel_launch(void* const* d_in, const int* in_sizes, int n_in,
                              void* d_out, int out_size) {
    const float* h = (const float*)d_in[0];
    const float* g = (const float*)d_in[1];

    // Weights -> constant memory (tiny async D2D copies; graph-capturable).
    cudaMemcpyToSymbolAsync(cWi_r, d_in[2], 16 * sizeof(float), 0, cudaMemcpyDeviceToDevice, 0);
    cudaMemcpyToSymbolAsync(cWh_r, d_in[3], 64 * sizeof(float), 0, cudaMemcpyDeviceToDevice, 0);
    cudaMemcpyToSymbolAsync(cbh_r, d_in[4],  8 * sizeof(float), 0, cudaMemcpyDeviceToDevice, 0);
    cudaMemcpyToSymbolAsync(cWi_z, d_in[5], 16 * sizeof(float), 0, cudaMemcpyDeviceToDevice, 0);
    cudaMemcpyToSymbolAsync(cWh_z, d_in[6], 64 * sizeof(float), 0, cudaMemcpyDeviceToDevice, 0);
    cudaMemcpyToSymbolAsync(cbh_z, d_in[7],  8 * sizeof(float), 0, cudaMemcpyDeviceToDevice, 0);
    cudaMemcpyToSymbolAsync(cWi_n, d_in[8], 16 * sizeof(float), 0, cudaMemcpyDeviceToDevice, 0);
    cudaMemcpyToSymbolAsync(cWh_n, d_in[9], 64 * sizeof(float), 0, cudaMemcpyDeviceToDevice, 0);
    cudaMemcpyToSymbolAsync(cbh_n, d_in[10], 8 * sizeof(float), 0, cudaMemcpyDeviceToDevice, 0);
    cudaMemcpyToSymbolAsync(cWm,   d_in[11], 8 * sizeof(float), 0, cudaMemcpyDeviceToDevice, 0);
    cudaMemcpyToSymbolAsync(cbm,   d_in[12], 1 * sizeof(float), 0, cudaMemcpyDeviceToDevice, 0);

    int N = in_sizes[1];  // g has N elements
    float* out   = (float*)d_out;
    float* out_h = out;                       // [N, 8] row-major
    float* out_o = out + (size_t)N * HID;     // [N]

    int blocks = (N + ROWS_PER_BLOCK - 1) / ROWS_PER_BLOCK;  // 128 thr x 2 rows
    l2o_gru_kernel<<<blocks, TPB>>>(h, g, out_h, out_o, N);
}